// round 16
// baseline (speedup 1.0000x reference)
#include <cuda_runtime.h>

#define B_  2
#define DD  64
#define HH  256
#define WW  256
#define HW  (HH*WW)
#define DHW (DD*HW)
#define PD  (DD+2)
#define PH  (HH+2)
#define PW  (WW+2)
#define PHW (PH*PW)      // 66564

// Zero-padded moving channel (channel 0), per batch. 35.1 MB.
// Borders are NEVER written: they remain exactly 0.0f from static
// zero-initialization (deterministic across graph replays).
__device__ float g_xpad[B_ * PD * PHW];

// Conv weights/bias in constant memory (filled by async D2D copy at launch).
__constant__ float cw[162];
__constant__ float cb[3];

// ---------------------------------------------------------------------------
// Kernel 1: copy the moving channel into the interior of the padded volume.
// Grid (HH/4, DD, B_), 256 threads; each thread copies one column across 4
// consecutive y-rows (MLP=4, warp-contiguous). Write-back stores keep xpad
// warm in L2 for the gather kernel.
// ---------------------------------------------------------------------------
__global__ void __launch_bounds__(256) pad_kernel(const float* __restrict__ x) {
    const int y0 = blockIdx.x << 2;    // 0..HH-4
    const int z  = blockIdx.y;         // 0..DD-1
    const int b  = blockIdx.z;         // 0..B_-1
    const int xi = threadIdx.x;        // 0..WW-1

    const float* src = x + (size_t)b * 2 * DHW + (size_t)z * HW + (size_t)y0 * WW + xi;
    float* dst = g_xpad + (size_t)b * PD * PHW + (size_t)(z + 1) * PHW
               + (size_t)(y0 + 1) * PW + (xi + 1);

    float v0 = __ldcs(src);
    float v1 = __ldcs(src + WW);
    float v2 = __ldcs(src + 2 * WW);
    float v3 = __ldcs(src + 3 * WW);
    dst[0]      = v0;
    dst[PW]     = v1;
    dst[2 * PW] = v2;
    dst[3 * PW] = v3;
}

// ---------------------------------------------------------------------------
// Kernel 2: fused offset-conv + trilinear deformable sampling + fixed copy.
// Byte-identical math to the passing R14/R15 kernel (lane = x; 2 z x 4 y
// outputs per thread; sliding-row conv, per-accumulator tap order kz asc ->
// ky asc -> kx asc -> c innermost, exact-zero OOB taps -> bit-identical).
// Single delta vs R15: __launch_bounds__(256, 6) to push occupancy from 5 to
// 6 blocks/SM (42-reg target) and hide more gather latency.
// ---------------------------------------------------------------------------
__global__ void __launch_bounds__(256, 6) reg3d_kernel(
    const float* __restrict__ x,
    float* __restrict__ out)        // [2, 2, 64, 256, 256]
{
    const int t = threadIdx.x;             // xi = t (0..255)
    const int blk = blockIdx.x;            // 4096 = 64(yq) * 32(zp) * 2(b)
    const int yq = blk & 63;
    const int zp = (blk >> 6) & 31;
    const int b  = blk >> 11;
    const int z0 = zp << 1;                // first of 2 z outputs
    const int y0 = yq << 2;                // first of 4 y outputs

    const int xi = t;
    const float* xb = x + (size_t)b * 2 * DHW;

    // bounds predicates
    bool pp[4], py[6];
    #pragma unroll
    for (int p = 0; p < 4; p++)  pp[p] = (unsigned)(z0 - 1 + p) < (unsigned)DD;
    #pragma unroll
    for (int dy = 0; dy < 6; dy++) py[dy] = (unsigned)(y0 - 1 + dy) < (unsigned)HH;
    const bool pxm = (xi >= 1), pxp = (xi < 255);

    // base at (z0-1, y0-1, xi)
    const float* base = xb + (ptrdiff_t)(z0 - 1) * HW + (ptrdiff_t)(y0 - 1) * WW + xi;

    // accumulators: [out-ch][zz][j]
    float a0[2][4], a1[2][4], a2[2][4];
    #pragma unroll
    for (int zz = 0; zz < 2; zz++)
        #pragma unroll
        for (int j = 0; j < 4; j++) { a0[zz][j] = 0.f; a1[zz][j] = 0.f; a2[zz][j] = 0.f; }

    #pragma unroll
    for (int p = 0; p < 4; p++) {
        #pragma unroll
        for (int dy = 0; dy < 6; dy++) {
            const bool rowok = pp[p] && py[dy];
            const float* q = base + (ptrdiff_t)p * HW + (ptrdiff_t)dy * WW;
            float trip[2][3];
            #pragma unroll
            for (int c = 0; c < 2; c++) {
                const float* qc = q + (ptrdiff_t)c * DHW;
                trip[c][0] = (rowok && pxm) ? __ldcs(qc - 1) : 0.f;
                trip[c][1] = rowok          ? __ldcs(qc)     : 0.f;
                trip[c][2] = (rowok && pxp) ? __ldcs(qc + 1) : 0.f;
            }

            #pragma unroll
            for (int ky = 0; ky < 3; ky++) {
                const int j = dy - ky;
                if (j < 0 || j > 3) continue;
                #pragma unroll
                for (int zz = 0; zz < 2; zz++) {
                    const int kz = p - zz;
                    if (kz < 0 || kz > 2) continue;
                    #pragma unroll
                    for (int kx = 0; kx < 3; kx++)
                        #pragma unroll
                        for (int c = 0; c < 2; c++) {
                            const int wo = c * 27 + kz * 9 + ky * 3 + kx;
                            const float v = trip[c][kx];
                            a0[zz][j] = __fmaf_rn(v, cw[wo],       a0[zz][j]);
                            a1[zz][j] = __fmaf_rn(v, cw[54 + wo],  a1[zz][j]);
                            a2[zz][j] = __fmaf_rn(v, cw[108 + wo], a2[zz][j]);
                        }
                }
            }
        }
    }

    // ---- sampling (op-for-op faithful) ----
    const float* xpad = g_xpad + (size_t)b * PD * PHW;
    const float b0 = cb[0], b1 = cb[1], b2 = cb[2];

    #pragma unroll
    for (int zz = 0; zz < 2; zz++) {
        const int z = z0 + zz;
        const size_t rowbase = (size_t)b * 2 * DHW + (size_t)z * HW;
        #pragma unroll
        for (int j = 0; j < 4; j++) {
            const int y = y0 + j;
            float oz = __fadd_rn(a0[zz][j], b0);
            float oy = __fadd_rn(a1[zz][j], b1);
            float ox = __fadd_rn(a2[zz][j], b2);

            float qz = fminf(fmaxf(__fadd_rn((float)(z + 1), oz), 0.f), 64.f);
            float qy = fminf(fmaxf(__fadd_rn((float)(y + 1), oy), 0.f), 256.f);
            float qx = fminf(fmaxf(__fadd_rn((float)(xi + 1), ox), 0.f), 256.f);

            float lz = __fadd_rn(qz, -floorf(qz));
            float ly = __fadd_rn(qy, -floorf(qy));
            float lx = __fadd_rn(qx, -floorf(qx));
            float wz0 = __fadd_rn(1.f, -lz);
            float wy0 = __fadd_rn(1.f, -ly);
            float wx0 = __fadd_rn(1.f, -lx);

            float acc = 0.f;
            #pragma unroll
            for (int dz = 0; dz < 2; dz++) {
                float cz = __fadd_rn(qz, (float)dz);
                float wz = dz ? lz : wz0;
                float czp = __fmul_rn(cz, (float)PHW);
                #pragma unroll
                for (int dy = 0; dy < 2; dy++) {
                    float cy  = __fadd_rn(qy, (float)dy);
                    float wzy = __fmul_rn(wz, dy ? ly : wy0);
                    float czyp = __fadd_rn(czp, __fmul_rn(cy, (float)PW));
                    #pragma unroll
                    for (int dx = 0; dx < 2; dx++) {
                        float cx   = __fadd_rn(qx, (float)dx);
                        float comb = __fadd_rn(czyp, cx);
                        unsigned idx = (unsigned)comb;   // trunc (astype int32)
                        float wv = __fmul_rn(wzy, dx ? lx : wx0);
                        acc = __fadd_rn(acc, __fmul_rn(__ldg(xpad + idx), wv));
                    }
                }
            }

            const size_t o0 = rowbase + (size_t)y * WW + xi;
            __stcs(out + o0, acc);                                            // deformed
            __stcs(out + o0 + DHW,
                   __ldcs(xb + DHW + (size_t)z * HW + (size_t)y * WW + xi));  // fixed
        }
    }
}

// ---------------------------------------------------------------------------
extern "C" void kernel_launch(void* const* d_in, const int* in_sizes, int n_in,
                              void* d_out, int out_size) {
    const float* x  = (const float*)d_in[0];
    const float* wp = (const float*)d_in[1];
    const float* bp = (const float*)d_in[2];
    float* out = (float*)d_out;

    // weights/bias -> constant bank (device-to-device, graph-capturable)
    cudaMemcpyToSymbolAsync(cw, wp, 162 * sizeof(float), 0, cudaMemcpyDeviceToDevice);
    cudaMemcpyToSymbolAsync(cb, bp, 3 * sizeof(float), 0, cudaMemcpyDeviceToDevice);

    dim3 pgrid(HH / 4, DD, B_);
    pad_kernel<<<pgrid, 256>>>(x);

    // 2(b) * 32(z-pairs) * 64(y-quads) = 4096 blocks, 256 threads = full x row
    reg3d_kernel<<<4096, 256>>>(x, out);
}

// round 17
// speedup vs baseline: 1.1449x; 1.1449x over previous
#include <cuda_runtime.h>

#define B_  2
#define DD  64
#define HH  256
#define WW  256
#define HW  (HH*WW)
#define DHW (DD*HW)
#define PD  (DD+2)
#define PH  (HH+2)
#define PW  (WW+2)
#define PHW (PH*PW)      // 66564

// Zero-padded moving channel (channel 0), per batch. 35.1 MB.
// Borders are NEVER written: they remain exactly 0.0f from static
// zero-initialization (deterministic across graph replays).
__device__ float g_xpad[B_ * PD * PHW];

// Conv weights/bias in constant memory (filled by async D2D copy at launch).
__constant__ float cw[162];
__constant__ float cb[3];

// ---------------------------------------------------------------------------
// Kernel 1: copy the moving channel into the interior of the padded volume.
// Grid (HH/8, DD, B_), 256 threads; each thread copies one column across 8
// consecutive y-rows (MLP=8, all warp-contiguous). Write-back stores keep
// xpad warm in L2 for the gather kernel.
// ---------------------------------------------------------------------------
__global__ void __launch_bounds__(256) pad_kernel(const float* __restrict__ x) {
    const int y0 = blockIdx.x << 3;    // 0..HH-8
    const int z  = blockIdx.y;         // 0..DD-1
    const int b  = blockIdx.z;         // 0..B_-1
    const int xi = threadIdx.x;        // 0..WW-1

    const float* src = x + (size_t)b * 2 * DHW + (size_t)z * HW + (size_t)y0 * WW + xi;
    float* dst = g_xpad + (size_t)b * PD * PHW + (size_t)(z + 1) * PHW
               + (size_t)(y0 + 1) * PW + (xi + 1);

    float v[8];
    #pragma unroll
    for (int j = 0; j < 8; j++) v[j] = __ldcs(src + j * WW);
    #pragma unroll
    for (int j = 0; j < 8; j++) dst[j * PW] = v[j];
}

// ---------------------------------------------------------------------------
// Kernel 2: fused offset-conv + trilinear deformable sampling + fixed copy.
// Byte-identical to the passing R15 kernel (lane = x; 2 z x 4 y outputs per
// thread; sliding-row conv with per-accumulator tap order kz asc -> ky asc ->
// kx asc -> c innermost and exact-zero OOB taps -> bit-identical results).
// 48 regs / 5 blocks/SM — measured optimum (R12: 64r/46% and R16: 40r/69%
// both equal or worse).
// ---------------------------------------------------------------------------
__global__ void __launch_bounds__(256) reg3d_kernel(
    const float* __restrict__ x,
    float* __restrict__ out)        // [2, 2, 64, 256, 256]
{
    const int t = threadIdx.x;             // xi = t (0..255)
    const int blk = blockIdx.x;            // 4096 = 64(yq) * 32(zp) * 2(b)
    const int yq = blk & 63;
    const int zp = (blk >> 6) & 31;
    const int b  = blk >> 11;
    const int z0 = zp << 1;                // first of 2 z outputs
    const int y0 = yq << 2;                // first of 4 y outputs

    const int xi = t;
    const float* xb = x + (size_t)b * 2 * DHW;

    // bounds predicates
    bool pp[4], py[6];
    #pragma unroll
    for (int p = 0; p < 4; p++)  pp[p] = (unsigned)(z0 - 1 + p) < (unsigned)DD;
    #pragma unroll
    for (int dy = 0; dy < 6; dy++) py[dy] = (unsigned)(y0 - 1 + dy) < (unsigned)HH;
    const bool pxm = (xi >= 1), pxp = (xi < 255);

    // base at (z0-1, y0-1, xi)
    const float* base = xb + (ptrdiff_t)(z0 - 1) * HW + (ptrdiff_t)(y0 - 1) * WW + xi;

    // accumulators: [out-ch][zz][j]
    float a0[2][4], a1[2][4], a2[2][4];
    #pragma unroll
    for (int zz = 0; zz < 2; zz++)
        #pragma unroll
        for (int j = 0; j < 4; j++) { a0[zz][j] = 0.f; a1[zz][j] = 0.f; a2[zz][j] = 0.f; }

    #pragma unroll
    for (int p = 0; p < 4; p++) {
        #pragma unroll
        for (int dy = 0; dy < 6; dy++) {
            const bool rowok = pp[p] && py[dy];
            const float* q = base + (ptrdiff_t)p * HW + (ptrdiff_t)dy * WW;
            float trip[2][3];
            #pragma unroll
            for (int c = 0; c < 2; c++) {
                const float* qc = q + (ptrdiff_t)c * DHW;
                trip[c][0] = (rowok && pxm) ? __ldcs(qc - 1) : 0.f;
                trip[c][1] = rowok          ? __ldcs(qc)     : 0.f;
                trip[c][2] = (rowok && pxp) ? __ldcs(qc + 1) : 0.f;
            }

            #pragma unroll
            for (int ky = 0; ky < 3; ky++) {
                const int j = dy - ky;
                if (j < 0 || j > 3) continue;
                #pragma unroll
                for (int zz = 0; zz < 2; zz++) {
                    const int kz = p - zz;
                    if (kz < 0 || kz > 2) continue;
                    #pragma unroll
                    for (int kx = 0; kx < 3; kx++)
                        #pragma unroll
                        for (int c = 0; c < 2; c++) {
                            const int wo = c * 27 + kz * 9 + ky * 3 + kx;
                            const float v = trip[c][kx];
                            a0[zz][j] = __fmaf_rn(v, cw[wo],       a0[zz][j]);
                            a1[zz][j] = __fmaf_rn(v, cw[54 + wo],  a1[zz][j]);
                            a2[zz][j] = __fmaf_rn(v, cw[108 + wo], a2[zz][j]);
                        }
                }
            }
        }
    }

    // ---- sampling (op-for-op faithful) ----
    const float* xpad = g_xpad + (size_t)b * PD * PHW;
    const float b0 = cb[0], b1 = cb[1], b2 = cb[2];

    #pragma unroll
    for (int zz = 0; zz < 2; zz++) {
        const int z = z0 + zz;
        const size_t rowbase = (size_t)b * 2 * DHW + (size_t)z * HW;
        #pragma unroll
        for (int j = 0; j < 4; j++) {
            const int y = y0 + j;
            float oz = __fadd_rn(a0[zz][j], b0);
            float oy = __fadd_rn(a1[zz][j], b1);
            float ox = __fadd_rn(a2[zz][j], b2);

            float qz = fminf(fmaxf(__fadd_rn((float)(z + 1), oz), 0.f), 64.f);
            float qy = fminf(fmaxf(__fadd_rn((float)(y + 1), oy), 0.f), 256.f);
            float qx = fminf(fmaxf(__fadd_rn((float)(xi + 1), ox), 0.f), 256.f);

            float lz = __fadd_rn(qz, -floorf(qz));
            float ly = __fadd_rn(qy, -floorf(qy));
            float lx = __fadd_rn(qx, -floorf(qx));
            float wz0 = __fadd_rn(1.f, -lz);
            float wy0 = __fadd_rn(1.f, -ly);
            float wx0 = __fadd_rn(1.f, -lx);

            float acc = 0.f;
            #pragma unroll
            for (int dz = 0; dz < 2; dz++) {
                float cz = __fadd_rn(qz, (float)dz);
                float wz = dz ? lz : wz0;
                float czp = __fmul_rn(cz, (float)PHW);
                #pragma unroll
                for (int dy = 0; dy < 2; dy++) {
                    float cy  = __fadd_rn(qy, (float)dy);
                    float wzy = __fmul_rn(wz, dy ? ly : wy0);
                    float czyp = __fadd_rn(czp, __fmul_rn(cy, (float)PW));
                    #pragma unroll
                    for (int dx = 0; dx < 2; dx++) {
                        float cx   = __fadd_rn(qx, (float)dx);
                        float comb = __fadd_rn(czyp, cx);
                        unsigned idx = (unsigned)comb;   // trunc (astype int32)
                        float wv = __fmul_rn(wzy, dx ? lx : wx0);
                        acc = __fadd_rn(acc, __fmul_rn(__ldg(xpad + idx), wv));
                    }
                }
            }

            const size_t o0 = rowbase + (size_t)y * WW + xi;
            __stcs(out + o0, acc);                                            // deformed
            __stcs(out + o0 + DHW,
                   __ldcs(xb + DHW + (size_t)z * HW + (size_t)y * WW + xi));  // fixed
        }
    }
}

// ---------------------------------------------------------------------------
extern "C" void kernel_launch(void* const* d_in, const int* in_sizes, int n_in,
                              void* d_out, int out_size) {
    const float* x  = (const float*)d_in[0];
    const float* wp = (const float*)d_in[1];
    const float* bp = (const float*)d_in[2];
    float* out = (float*)d_out;

    // weights/bias -> constant bank (device-to-device, graph-capturable)
    cudaMemcpyToSymbolAsync(cw, wp, 162 * sizeof(float), 0, cudaMemcpyDeviceToDevice);
    cudaMemcpyToSymbolAsync(cb, bp, 3 * sizeof(float), 0, cudaMemcpyDeviceToDevice);

    dim3 pgrid(HH / 8, DD, B_);
    pad_kernel<<<pgrid, 256>>>(x);

    // 2(b) * 32(z-pairs) * 64(y-quads) = 4096 blocks, 256 threads = full x row
    reg3d_kernel<<<4096, 256>>>(x, out);
}